// round 1
// baseline (speedup 1.0000x reference)
#include <cuda_runtime.h>
#include <cuda_bf16.h>
#include <math.h>

// Problem constants (fixed-shape dataset: seq (256,40) int32, sim (512,512) f32,
// pers (512,512,512) f32, weights (2,) f32, output scalar f32).
constexpr int V = 512;
constexpr int B = 256;
constexpr int L = 40;
constexpr int ROWS = B * (L - 1);   // 9984 (b,t) positions

__device__ __forceinline__ float warp_max(float v) {
    #pragma unroll
    for (int o = 16; o; o >>= 1) v = fmaxf(v, __shfl_xor_sync(0xffffffffu, v, o));
    return v;
}
__device__ __forceinline__ float warp_sum(float v) {
    #pragma unroll
    for (int o = 16; o; o >>= 1) v += __shfl_xor_sync(0xffffffffu, v, o);
    return v;
}

__global__ void init_out_kernel(float* out) {
    // nll0 = B * log(V)
    out[0] = (float)B * logf((float)V);
}

__global__ __launch_bounds__(128)
void nll_kernel(const int* __restrict__ seq,
                const float* __restrict__ sim,
                const float* __restrict__ pers,
                const float* __restrict__ w,
                float* __restrict__ out) {
    const int row = blockIdx.x;          // 0 .. ROWS-1
    const int b   = row / (L - 1);
    const int t   = row % (L - 1);

    const int prev = seq[b * L + t];
    const int tgt  = seq[b * L + t + 1];
    const float w0 = w[0];
    const float w1 = w[1];

    const int tid  = threadIdx.x;        // 128 threads, 4 floats each
    const int lane = tid & 31;
    const int wid  = tid >> 5;

    // logits[tid*4 .. tid*4+3] = w0 * sim[prev, :] (+ w1 * pers[p0, prev, :] for t>=1)
    const float4 s = reinterpret_cast<const float4*>(sim + (size_t)prev * V)[tid];
    float4 lg;
    lg.x = w0 * s.x; lg.y = w0 * s.y; lg.z = w0 * s.z; lg.w = w0 * s.w;

    if (t >= 1) {
        const int p0 = seq[b * L + t - 1];
        const float4 p = reinterpret_cast<const float4*>(
            pers + ((size_t)p0 * V + (size_t)prev) * V)[tid];
        lg.x += w1 * p.x; lg.y += w1 * p.y; lg.z += w1 * p.z; lg.w += w1 * p.w;
    }

    __shared__ float sh_max[4];
    __shared__ float sh_sum[4];
    __shared__ float sh_tgt;

    // stash the target logit
    if (tid == (tgt >> 2)) {
        const int c = tgt & 3;
        sh_tgt = (c == 0) ? lg.x : (c == 1) ? lg.y : (c == 2) ? lg.z : lg.w;
    }

    // block max
    float m = fmaxf(fmaxf(lg.x, lg.y), fmaxf(lg.z, lg.w));
    m = warp_max(m);
    if (lane == 0) sh_max[wid] = m;
    __syncthreads();
    m = fmaxf(fmaxf(sh_max[0], sh_max[1]), fmaxf(sh_max[2], sh_max[3]));

    // block sum of exp(x - m)
    float e = expf(lg.x - m) + expf(lg.y - m) + expf(lg.z - m) + expf(lg.w - m);
    e = warp_sum(e);
    if (lane == 0) sh_sum[wid] = e;
    __syncthreads();

    if (tid == 0) {
        const float ssum = sh_sum[0] + sh_sum[1] + sh_sum[2] + sh_sum[3];
        // -logp[target] = -(logit_tgt - m - log(sum))
        const float nll = -(sh_tgt - m - logf(ssum));
        atomicAdd(out, nll);
    }
}

extern "C" void kernel_launch(void* const* d_in, const int* in_sizes, int n_in,
                              void* d_out, int out_size) {
    const int*   seq  = (const int*)  d_in[0];
    const float* sim  = (const float*)d_in[1];
    const float* pers = (const float*)d_in[2];
    const float* w    = (const float*)d_in[3];
    float* out = (float*)d_out;

    init_out_kernel<<<1, 1>>>(out);
    nll_kernel<<<ROWS, 128>>>(seq, sim, pers, w, out);
}

// round 2
// speedup vs baseline: 2.2438x; 2.2438x over previous
#include <cuda_runtime.h>
#include <cuda_bf16.h>
#include <math.h>

// Fixed shapes: seq (256,40) int32, sim (512,512) f32, pers (512,512,512) f32,
// weights (2,) f32, output scalar f32.
constexpr int V = 512;
constexpr int B = 256;
constexpr int L = 40;
constexpr int ROWS = B * (L - 1);        // 9984
constexpr int WARPS_PER_BLOCK = 8;       // 8 rows per 256-thread block
constexpr int NBLOCKS = ROWS / WARPS_PER_BLOCK;  // 1248

__global__ void init_out_kernel(float* out) {
    out[0] = (float)B * logf((float)V);  // nll0
}

__global__ __launch_bounds__(256)
void nll_kernel(const int* __restrict__ seq,
                const float* __restrict__ sim,
                const float* __restrict__ pers,
                const float* __restrict__ w,
                float* __restrict__ out) {
    const int warp = threadIdx.x >> 5;
    const int lane = threadIdx.x & 31;
    const int row  = blockIdx.x * WARPS_PER_BLOCK + warp;   // 0..ROWS-1
    const int b = row / (L - 1);
    const int t = row % (L - 1);
    const int base = b * L + t;

    const int prev = seq[base];
    const int tgt  = seq[base + 1];
    const float w0 = w[0];
    const float w1 = w[1];

    // Each lane owns elements (lane + 32*i)*4 + c, i in [0,4), c in [0,4).
    const float4* srow = reinterpret_cast<const float4*>(sim + (size_t)prev * V);
    float4 sv[4];
    #pragma unroll
    for (int i = 0; i < 4; i++) sv[i] = srow[lane + 32 * i];

    float4 pv[4];
    if (t >= 1) {
        const int p0 = seq[base - 1];
        const float4* prow = reinterpret_cast<const float4*>(
            pers + ((size_t)p0 * V + (size_t)prev) * V);
        #pragma unroll
        for (int i = 0; i < 4; i++) pv[i] = prow[lane + 32 * i];
    } else {
        #pragma unroll
        for (int i = 0; i < 4; i++) pv[i] = make_float4(0.f, 0.f, 0.f, 0.f);
    }

    // logits = w0*sim + w1*pers; accumulate sum(exp(x)) directly (|x| <~ 8, safe in f32)
    const int tgt_i    = tgt >> 7;          // which chunk
    const int tgt_c    = tgt & 3;           // which component
    const int tgt_lane = (tgt >> 2) & 31;   // which lane owns it

    float sumexp = 0.f;
    float tgt_val = 0.f;
    #pragma unroll
    for (int i = 0; i < 4; i++) {
        float x0 = fmaf(w1, pv[i].x, w0 * sv[i].x);
        float x1 = fmaf(w1, pv[i].y, w0 * sv[i].y);
        float x2 = fmaf(w1, pv[i].z, w0 * sv[i].z);
        float x3 = fmaf(w1, pv[i].w, w0 * sv[i].w);
        sumexp += __expf(x0) + __expf(x1) + __expf(x2) + __expf(x3);
        if (i == tgt_i) {
            float v = (tgt_c == 0) ? x0 : (tgt_c == 1) ? x1 : (tgt_c == 2) ? x2 : x3;
            tgt_val = v;   // only meaningful on tgt_lane
        }
    }

    // warp-reduce sumexp; broadcast target logit from owning lane
    #pragma unroll
    for (int o = 16; o; o >>= 1) sumexp += __shfl_xor_sync(0xffffffffu, sumexp, o);
    tgt_val = __shfl_sync(0xffffffffu, tgt_val, tgt_lane);

    // nll = log(sum exp x) - x_tgt
    __shared__ float sh[WARPS_PER_BLOCK];
    if (lane == 0) sh[warp] = __logf(sumexp) - tgt_val;
    __syncthreads();

    if (threadIdx.x == 0) {
        float acc = 0.f;
        #pragma unroll
        for (int i = 0; i < WARPS_PER_BLOCK; i++) acc += sh[i];
        atomicAdd(out, acc);
    }
}

extern "C" void kernel_launch(void* const* d_in, const int* in_sizes, int n_in,
                              void* d_out, int out_size) {
    const int*   seq  = (const int*)  d_in[0];
    const float* sim  = (const float*)d_in[1];
    const float* pers = (const float*)d_in[2];
    const float* w    = (const float*)d_in[3];
    float* out = (float*)d_out;

    init_out_kernel<<<1, 1>>>(out);
    nll_kernel<<<NBLOCKS, 256>>>(seq, sim, pers, w, out);
}